// round 1
// baseline (speedup 1.0000x reference)
#include <cuda_runtime.h>

// out[c] = sum_{i,j} w[i,j,c] * inputs[0,i,j,c]
// H = W = 512, C = 256, batch = 2 (only batch 0 used).
// Pure streaming: 512 MB read -> HBM-bound.

#define NPOS        (512 * 512)       // spatial positions
#define GRID_BLOCKS 1024
#define POS_PER_BLK (NPOS / GRID_BLOCKS)   // 256
#define C4          64                // 256 channels as 64 float4

__global__ void zero_out_kernel(float* out) {
    out[threadIdx.x] = 0.0f;
}

__global__ __launch_bounds__(256, 8)
void chan_dot_kernel(const float4* __restrict__ in,
                     const float4* __restrict__ w,
                     float* __restrict__ out) {
    const int c4 = threadIdx.x;   // 0..63  (channel quad)
    const int ys = threadIdx.y;   // 0..3   (position sub-lane)
    const int base_pos = blockIdx.x * POS_PER_BLK;

    float ax = 0.f, ay = 0.f, az = 0.f, aw = 0.f;

    // Each (ys) lane strides positions by 4; unroll for MLP.
    #pragma unroll 4
    for (int p = ys; p < POS_PER_BLK; p += 4) {
        const int idx = (base_pos + p) * C4 + c4;   // float4 index, < 2^24
        const float4 a = __ldcs(in + idx);
        const float4 b = __ldcs(w  + idx);
        ax = fmaf(a.x, b.x, ax);
        ay = fmaf(a.y, b.y, ay);
        az = fmaf(a.z, b.z, az);
        aw = fmaf(a.w, b.w, aw);
    }

    // Reduce the 4 position-sub-lanes per channel quad via smem.
    __shared__ float4 s[4][C4];
    s[ys][c4] = make_float4(ax, ay, az, aw);
    __syncthreads();

    if (ys == 0) {
        float4 t0 = s[0][c4];
        float4 t1 = s[1][c4];
        float4 t2 = s[2][c4];
        float4 t3 = s[3][c4];
        float rx = (t0.x + t1.x) + (t2.x + t3.x);
        float ry = (t0.y + t1.y) + (t2.y + t3.y);
        float rz = (t0.z + t1.z) + (t2.z + t3.z);
        float rw = (t0.w + t1.w) + (t2.w + t3.w);
        atomicAdd(&out[c4 * 4 + 0], rx);
        atomicAdd(&out[c4 * 4 + 1], ry);
        atomicAdd(&out[c4 * 4 + 2], rz);
        atomicAdd(&out[c4 * 4 + 3], rw);
    }
}

extern "C" void kernel_launch(void* const* d_in, const int* in_sizes, int n_in,
                              void* d_out, int out_size) {
    const float4* in = (const float4*)d_in[0];   // (2, 512, 512, 256) f32; batch 0 only
    const float4* w  = (const float4*)d_in[1];   // (512, 512, 256) f32
    float* out = (float*)d_out;                  // 256 f32

    zero_out_kernel<<<1, 256>>>(out);
    dim3 block(C4, 4);
    chan_dot_kernel<<<GRID_BLOCKS, block>>>(in, w, out);
}

// round 3
// speedup vs baseline: 1.1369x; 1.1369x over previous
#include <cuda_runtime.h>

// out[c] = sum_{i,j} w[i,j,c] * inputs[0,i,j,c];  H=W=512, C=256, batch=2 (batch 0 only).
// Pure streaming reduction: 512 MB read -> HBM-bound.
// Key fix vs R1: launch_bounds(256,4) -> 64 regs -> 8 front-batched LDG.128 per thread.

#define NPOS        (512 * 512)
#define GRID_BLOCKS 1024
#define POS_PER_BLK (NPOS / GRID_BLOCKS)   // 256
#define C4          64                      // 256 channels as 64 float4

__global__ void zero_out_kernel(float* out) { out[threadIdx.x] = 0.0f; }

__global__ __launch_bounds__(256, 4)
void chan_dot_kernel(const float4* __restrict__ in,
                     const float4* __restrict__ w,
                     float* __restrict__ out) {
    const int tx = threadIdx.x & 63;   // channel quad
    const int ty = threadIdx.x >> 6;   // 0..3 position sub-lane
    const int base_pos = blockIdx.x * POS_PER_BLK;

    float ax = 0.f, ay = 0.f, az = 0.f, aw = 0.f;

    // Thread handles positions p = ty + 4*j, j = 0..63, in batches of 4.
    // Per batch: 8 independent LDG.E.128 front-batched (MLP_p1 = 8), then FMAs.
    #pragma unroll 1
    for (int k = 0; k < POS_PER_BLK / 16; k++) {      // 16 batches
        float4 a[4], b[4];
        #pragma unroll
        for (int u = 0; u < 4; u++) {
            const int p = ty + (k * 4 + u) * 4;       // position within block
            const int idx = (base_pos + p) * C4 + tx; // float4 index
            a[u] = __ldcs(in + idx);
            b[u] = __ldcs(w + idx);
        }
        #pragma unroll
        for (int u = 0; u < 4; u++) {
            ax = fmaf(a[u].x, b[u].x, ax);
            ay = fmaf(a[u].y, b[u].y, ay);
            az = fmaf(a[u].z, b[u].z, az);
            aw = fmaf(a[u].w, b[u].w, aw);
        }
    }

    // Reduce the 4 position sub-lanes per channel quad via smem, then atomics.
    __shared__ float4 s[4][C4];
    s[ty][tx] = make_float4(ax, ay, az, aw);
    __syncthreads();

    if (ty == 0) {
        const float4 t0 = s[0][tx];
        const float4 t1 = s[1][tx];
        const float4 t2 = s[2][tx];
        const float4 t3 = s[3][tx];
        atomicAdd(&out[tx * 4 + 0], (t0.x + t1.x) + (t2.x + t3.x));
        atomicAdd(&out[tx * 4 + 1], (t0.y + t1.y) + (t2.y + t3.y));
        atomicAdd(&out[tx * 4 + 2], (t0.z + t1.z) + (t2.z + t3.z));
        atomicAdd(&out[tx * 4 + 3], (t0.w + t1.w) + (t2.w + t3.w));
    }
}

extern "C" void kernel_launch(void* const* d_in, const int* in_sizes, int n_in,
                              void* d_out, int out_size) {
    const float4* in = (const float4*)d_in[0];   // (2,512,512,256) f32; batch 0 only
    const float4* w  = (const float4*)d_in[1];   // (512,512,256) f32
    float* out = (float*)d_out;                  // 256 f32

    zero_out_kernel<<<1, 256>>>(out);
    chan_dot_kernel<<<GRID_BLOCKS, 256>>>(in, w, out);
}

// round 4
// speedup vs baseline: 1.2513x; 1.1007x over previous
#include <cuda_runtime.h>

// out[c] = sum_{i,j} w[i,j,c] * inputs[0,i,j,c];  H=W=512, C=256, batch=2 (batch 0 only).
// Streaming reduction, HBM-bound. Persistent single-wave grid + register double-buffer.

#define NPOS   (512 * 512)
#define GRID   592                 // 148 SMs x 4 blocks: exactly one wave
#define UNITS  (NPOS / 8)          // work unit = 8 positions (2 per ty-lane); 32768 units

__global__ void zero_out_kernel(float* out) { out[threadIdx.x] = 0.0f; }

__global__ __launch_bounds__(256, 4)
void chan_dot_kernel(const float4* __restrict__ in,
                     const float4* __restrict__ w,
                     float* __restrict__ out) {
    const int tx = threadIdx.x & 63;   // channel quad
    const int ty = threadIdx.x >> 6;   // 0..3 position sub-lane

    float ax = 0.f, ay = 0.f, az = 0.f, aw = 0.f;

    float4 a0[2], b0[2], a1[2], b1[2];

    // Unit u covers positions [8u, 8u+8); thread handles positions 8u+2*ty+{0,1}.
    // Lane tx within a warp reads 512B contiguous per position -> fully coalesced.
#define LOADB(A, B, u) do {                               \
        const int _base = ((u) * 8 + ty * 2) * 64 + tx;   \
        A[0] = __ldcs(in + _base);                        \
        A[1] = __ldcs(in + _base + 64);                   \
        B[0] = __ldcs(w  + _base);                        \
        B[1] = __ldcs(w  + _base + 64);                   \
    } while (0)

#define FMAB(A, B) do {                                   \
        ax = fmaf(A[0].x, B[0].x, ax);                    \
        ay = fmaf(A[0].y, B[0].y, ay);                    \
        az = fmaf(A[0].z, B[0].z, az);                    \
        aw = fmaf(A[0].w, B[0].w, aw);                    \
        ax = fmaf(A[1].x, B[1].x, ax);                    \
        ay = fmaf(A[1].y, B[1].y, ay);                    \
        az = fmaf(A[1].z, B[1].z, az);                    \
        aw = fmaf(A[1].w, B[1].w, aw);                    \
    } while (0)

    int u = blockIdx.x;                 // < GRID <= UNITS, initial load always valid
    LOADB(a0, b0, u);
    for (;;) {
        const int u1 = u + GRID;
        if (u1 < UNITS) LOADB(a1, b1, u1);   // next batch in flight during these FMAs
        FMAB(a0, b0);
        if (u1 >= UNITS) break;

        const int u2 = u1 + GRID;
        if (u2 < UNITS) LOADB(a0, b0, u2);
        FMAB(a1, b1);
        if (u2 >= UNITS) break;
        u = u2;
    }

    // Reduce 4 position sub-lanes per channel quad via smem, then atomics.
    __shared__ float4 s[4][64];
    s[ty][tx] = make_float4(ax, ay, az, aw);
    __syncthreads();

    if (ty == 0) {
        const float4 t0 = s[0][tx];
        const float4 t1 = s[1][tx];
        const float4 t2 = s[2][tx];
        const float4 t3 = s[3][tx];
        atomicAdd(&out[tx * 4 + 0], (t0.x + t1.x) + (t2.x + t3.x));
        atomicAdd(&out[tx * 4 + 1], (t0.y + t1.y) + (t2.y + t3.y));
        atomicAdd(&out[tx * 4 + 2], (t0.z + t1.z) + (t2.z + t3.z));
        atomicAdd(&out[tx * 4 + 3], (t0.w + t1.w) + (t2.w + t3.w));
    }
}

extern "C" void kernel_launch(void* const* d_in, const int* in_sizes, int n_in,
                              void* d_out, int out_size) {
    const float4* in = (const float4*)d_in[0];   // (2,512,512,256) f32; batch 0 only
    const float4* w  = (const float4*)d_in[1];   // (512,512,256) f32
    float* out = (float*)d_out;                  // 256 f32

    zero_out_kernel<<<1, 256>>>(out);
    chan_dot_kernel<<<GRID, 256>>>(in, w, out);
}